// round 16
// baseline (speedup 1.0000x reference)
#include <cuda_runtime.h>
#include <cuda_fp16.h>
#include <cstdint>
#include <math.h>

// ---------------- problem constants ----------------
#define MODEL_DIM 1024
#define NUM_HEADS 16
#define HEAD_DIM  64
#define WINDOW    32
#define EPS       1e-5f
#define BATCH     2
#define SEQ       2048
#define MROWS     (BATCH * SEQ)      // 4096
#define QKV_LD    (3 * MODEL_DIM)    // 3072
#define KDIM      MODEL_DIM          // 1024
#define KT16      (KDIM / 16)        // 64

#define KNT 264                       // (2048+64)/8 n-tiles (padded)
#define VKT 132                       // (2048+64)/16 k-tiles (padded)

// ---------------- scratch (fragment-ordered fp16) ----------------
__device__ __half g_Hx  [(MROWS / 16) * KT16 * 256];
__device__ __half g_Wqkv[(QKV_LD / 8) * KT16 * 128];
__device__ __half g_Wo  [(MODEL_DIM / 8) * KT16 * 128];
__device__ float  g_bqkv[QKV_LD];
__device__ __half g_QfG [BATCH * NUM_HEADS * (SEQ / 16) * 1024];
__device__ __half g_KfG [BATCH * NUM_HEADS * KNT * 512];
__device__ __half g_VfG [BATCH * NUM_HEADS * 8 * VKT * 128];
__device__ __half g_ATTx[(MROWS / 16) * KT16 * 256];

// ---------------- helpers ----------------
__device__ __forceinline__ uint32_t smem_u32(const void* p) {
    uint32_t a;
    asm("{ .reg .u64 t; cvta.to.shared.u64 t, %1; cvt.u32.u64 %0, t; }" : "=r"(a) : "l"(p));
    return a;
}
__device__ __forceinline__ void cp_async16(uint32_t dst, const void* src) {
    asm volatile("cp.async.cg.shared.global [%0], [%1], 16;" :: "r"(dst), "l"(src) : "memory");
}
__device__ __forceinline__ void cp_commit() {
    asm volatile("cp.async.commit_group;" ::: "memory");
}
template<int N>
__device__ __forceinline__ void cp_wait() {
    asm volatile("cp.async.wait_group %0;" :: "n"(N) : "memory");
}
__device__ __forceinline__ void lds128(uint32_t* r, uint32_t a) {
    asm volatile("ld.shared.v4.b32 {%0,%1,%2,%3}, [%4];"
                 : "=r"(r[0]), "=r"(r[1]), "=r"(r[2]), "=r"(r[3]) : "r"(a));
}
__device__ __forceinline__ void lds64(uint32_t* r, uint32_t a) {
    asm volatile("ld.shared.v2.b32 {%0,%1}, [%2];"
                 : "=r"(r[0]), "=r"(r[1]) : "r"(a));
}
__device__ __forceinline__ void mma_f16(float* c, const uint32_t* a, const uint32_t* b) {
    asm volatile("mma.sync.aligned.m16n8k16.row.col.f32.f16.f16.f32 "
                 "{%0,%1,%2,%3},{%4,%5,%6,%7},{%8,%9},{%0,%1,%2,%3};"
                 : "+f"(c[0]), "+f"(c[1]), "+f"(c[2]), "+f"(c[3])
                 : "r"(a[0]), "r"(a[1]), "r"(a[2]), "r"(a[3]), "r"(b[0]), "r"(b[1]));
}

// fragment maps (half index within tile)
__device__ __forceinline__ int a_off_h(int rr, int cc) {
    return ((rr & 7) * 4 + ((cc & 7) >> 1)) * 8 + ((rr >> 3) + 2 * (cc >> 3)) * 2 + (cc & 1);
}
__device__ __forceinline__ int b_off_h(int k, int n) {
    return (n * 4 + ((k & 7) >> 1)) * 4 + (k >> 3) * 2 + (k & 1);
}
__device__ __forceinline__ int c_off(int rr, int cc) {
    return ((rr & 7) * 4 + (cc >> 1)) * 4 + (rr >> 3) * 2 + (cc & 1);
}

// ============================================================
// LayerNorm -> A-fragment-ordered fp16
// ============================================================
__global__ __launch_bounds__(256)
void ln_kernel(const float* __restrict__ x,
               const float* __restrict__ gamma,
               const float* __restrict__ beta,
               __half* __restrict__ Hx)
{
    int row = blockIdx.x;
    int tid = threadIdx.x;
    float4 a = ((const float4*)(x + (size_t)row * MODEL_DIM))[tid];

    __shared__ float red[8];
    __shared__ float stat;

    float s = a.x + a.y + a.z + a.w;
    #pragma unroll
    for (int o = 16; o; o >>= 1) s += __shfl_xor_sync(0xffffffffu, s, o);
    if ((tid & 31) == 0) red[tid >> 5] = s;
    __syncthreads();
    if (tid == 0) {
        float t = 0.f;
        #pragma unroll
        for (int i = 0; i < 8; i++) t += red[i];
        stat = t * (1.0f / MODEL_DIM);
    }
    __syncthreads();
    float mu = stat;

    float dx = a.x - mu, dy = a.y - mu, dz = a.z - mu, dw = a.w - mu;
    float s2 = dx*dx + dy*dy + dz*dz + dw*dw;
    #pragma unroll
    for (int o = 16; o; o >>= 1) s2 += __shfl_xor_sync(0xffffffffu, s2, o);
    __syncthreads();
    if ((tid & 31) == 0) red[tid >> 5] = s2;
    __syncthreads();
    if (tid == 0) {
        float t = 0.f;
        #pragma unroll
        for (int i = 0; i < 8; i++) t += red[i];
        stat = rsqrtf(t * (1.0f / MODEL_DIM) + EPS);
    }
    __syncthreads();
    float rstd = stat;

    float4 g = ((const float4*)gamma)[tid];
    float4 b = ((const float4*)beta)[tid];
    float v0 = dx * rstd * g.x + b.x;
    float v1 = dy * rstd * g.y + b.y;
    float v2 = dz * rstd * g.z + b.z;
    float v3 = dw * rstd * g.w + b.w;

    int mt = row >> 4, r = row & 15;
    int kt = tid >> 2;
    int cc0 = (tid * 4) & 15;
    __half* tile = Hx + ((size_t)mt * KT16 + kt) * 256;
    ((__half2*)tile)[a_off_h(r, cc0) >> 1]     = __floats2half2_rn(v0, v1);
    ((__half2*)tile)[a_off_h(r, cc0 + 2) >> 1] = __floats2half2_rn(v2, v3);
}

// ============================================================
// Weight -> B-fragment-ordered fp16
// ============================================================
__global__ __launch_bounds__(256)
void wconv_kernel(const float* __restrict__ wq, const float* __restrict__ wk,
                  const float* __restrict__ wv, const float* __restrict__ wo,
                  __half* __restrict__ Wqkv, __half* __restrict__ Wo)
{
    int bz = blockIdx.y;
    const float* w = (bz == 0) ? wq : (bz == 1) ? wk : (bz == 2) ? wv : wo;
    __half* WT = (bz < 3) ? (Wqkv + (size_t)bz * (1024 / 8) * KT16 * 128) : Wo;

    int idx = blockIdx.x * 256 + threadIdx.x;
    int k = idx >> 10;
    int n = idx & 1023;
    float v = w[idx];
    int nt = n >> 3, kt = k >> 4;
    WT[((size_t)nt * KT16 + kt) * 128 + b_off_h(k & 15, n & 7)] = __float2half_rn(v);
}

__global__ void bconcat_kernel(const float* __restrict__ bq,
                               const float* __restrict__ bk,
                               const float* __restrict__ bv,
                               float* __restrict__ dst)
{
    int i = blockIdx.x * 256 + threadIdx.x;
    if (i >= QKV_LD) return;
    const float* s = (i < 1024) ? bq : (i < 2048 ? bk : bv);
    dst[i] = s[i & 1023];
}

// ============================================================
// fp16 mma.sync GEMM. CTA 128x128x64, 8 warps (2m x 4n, 64x32),
// 2 CTA/SM (16 warps). A: 3-stage cp.async smem. B: direct
// coalesced LDG.64 of fragment-ordered global data.
// ============================================================
#define BM 128
#define BN 128
#define BK 64
#define A_TILE 16384                  // 8mt x 4kt x 512B
#define NSTAGE 3
#define NIT (KDIM / BK)               // 16
#define MM_SMEM (NSTAGE * A_TILE)     // 49152
#define MM_THREADS 256

__device__ __forceinline__ void stage_A(const __half* __restrict__ src,
                                        int mt0, int kt0, uint32_t dst)
{
    #pragma unroll
    for (int p = 0; p < 4; p++) {
        int ch = threadIdx.x + p * MM_THREADS;   // 1024 chunks of 16B
        int tl = ch >> 5;                        // 32 tiles (mti*4+kti)
        int in = ch & 31;
        int mti = tl >> 2, kti = tl & 3;
        const char* g = (const char*)(src + ((size_t)(mt0 + mti) * KT16 + kt0 + kti) * 256) + in * 16;
        cp_async16(dst + (uint32_t)tl * 512 + in * 16, g);
    }
}

template<int MODE>
__global__ __launch_bounds__(MM_THREADS, 2)
void mm_kernel(const __half* __restrict__ A,
               const __half* __restrict__ B,
               const float* __restrict__ bias,
               const float* __restrict__ resid,
               float* __restrict__ C, int ldc,
               __half* __restrict__ Qf, __half* __restrict__ Kf, __half* __restrict__ Vf)
{
    extern __shared__ char smem[];
    uint32_t sb = smem_u32(smem);

    int tid  = threadIdx.x;
    int wid  = tid >> 5;
    int lane = tid & 31;
    int mtb = (wid >> 2) * 4;            // 2 m-groups of 4 mt (64 rows)
    int ntb = (wid & 3) * 4;             // 4 n-groups of 4 nt (32 cols)
    int mt0 = blockIdx.y * 8;
    int nt0 = blockIdx.x * 16;

    float acc[4][4][4];
    #pragma unroll
    for (int i = 0; i < 4; i++)
        #pragma unroll
        for (int j = 0; j < 4; j++)
            #pragma unroll
            for (int q = 0; q < 4; q++) acc[i][j][q] = 0.f;

    stage_A(A, mt0, 0, sb);
    cp_commit();
    stage_A(A, mt0, 4, sb + A_TILE);
    cp_commit();

    uint32_t aoff = (uint32_t)lane * 16;
    // B fragment tile = 128 halves = 32 uint2; thread L's fragment = tile_base + L.
    const uint2* Bbase = (const uint2*)(B + ((size_t)(nt0 + ntb) * KT16) * 128) + lane;

    #pragma unroll 1
    for (int it = 0; it < NIT; it++) {
        cp_wait<1>();
        __syncthreads();

        if (it + 2 < NIT) {
            uint32_t nb = sb + (uint32_t)((it + 2) % NSTAGE) * A_TILE;
            stage_A(A, mt0, (it + 2) * 4, nb);
        }
        cp_commit();

        uint32_t aB = sb + (uint32_t)(it % NSTAGE) * A_TILE;

        #pragma unroll
        for (int kti = 0; kti < 4; kti++) {
            int ktg = it * 4 + kti;
            uint32_t af[4][4];
            uint2 bv[4];
            #pragma unroll
            for (int j = 0; j < 4; j++)
                bv[j] = __ldg(Bbase + ((size_t)j * KT16 + ktg) * 32);
            #pragma unroll
            for (int i = 0; i < 4; i++)
                lds128(af[i], aB + (uint32_t)((mtb + i) * 4 + kti) * 512 + aoff);
            #pragma unroll
            for (int i = 0; i < 4; i++)
                #pragma unroll
                for (int j = 0; j < 4; j++) {
                    uint32_t br[2] = {bv[j].x, bv[j].y};
                    mma_f16(acc[i][j], af[i], br);
                }
        }
    }

    int mBase = mt0 * 16 + mtb * 16 + (lane >> 2);
    int nBase = nt0 * 8 + ntb * 8 + (lane & 3) * 2;

    if (MODE == 1) {
        #pragma unroll
        for (int i = 0; i < 4; i++) {
            int m0 = mBase + i * 16;
            #pragma unroll
            for (int j = 0; j < 4; j++) {
                int n = nBase + j * 8;
                float bx0 = bias[n], bx1 = bias[n + 1];
                float2 v0, v1;
                v0.x = acc[i][j][0] + bx0;
                v0.y = acc[i][j][1] + bx1;
                v1.x = acc[i][j][2] + bx0;
                v1.y = acc[i][j][3] + bx1;
                float2 r0 = *(const float2*)(resid + (size_t)m0 * MODEL_DIM + n);
                float2 r1 = *(const float2*)(resid + (size_t)(m0 + 8) * MODEL_DIM + n);
                v0.x += r0.x; v0.y += r0.y;
                v1.x += r1.x; v1.y += r1.y;
                *(float2*)(C + (size_t)m0 * ldc + n)       = v0;
                *(float2*)(C + (size_t)(m0 + 8) * ldc + n) = v1;
            }
        }
    } else {
        int mtype = (nt0 * 8) >> 10;   // 0=Q 1=K 2=V (uniform per CTA)
        #pragma unroll
        for (int i = 0; i < 4; i++) {
            int m0 = mBase + i * 16;
            int bb  = m0 >> 11;
            int tok = m0 & 2047;
            #pragma unroll
            for (int j = 0; j < 4; j++) {
                int n = nBase + j * 8;
                float bx0 = bias[n], bx1 = bias[n + 1];
                float va0 = acc[i][j][0] + bx0, vb0 = acc[i][j][1] + bx1;
                float va1 = acc[i][j][2] + bx0, vb1 = acc[i][j][3] + bx1;
                int nn = n & 1023;
                int h = nn >> 6, d = nn & 63;
                int bh = bb * NUM_HEADS + h;
                if (mtype == 0) {
                    int kt = d >> 4, cc = d & 15;
                    __half2 h0 = __floats2half2_rn(va0 * 0.125f, vb0 * 0.125f);
                    __half2 h1 = __floats2half2_rn(va1 * 0.125f, vb1 * 0.125f);
                    __half* t0 = Qf + ((size_t)(bh * (SEQ / 16) + (tok >> 4))) * 1024 + kt * 256;
                    __half* t1 = Qf + ((size_t)(bh * (SEQ / 16) + ((tok + 8) >> 4))) * 1024 + kt * 256;
                    ((__half2*)t0)[a_off_h(tok & 15, cc) >> 1]       = h0;
                    ((__half2*)t1)[a_off_h((tok + 8) & 15, cc) >> 1] = h1;
                } else if (mtype == 1) {
                    int kt = d >> 4;
                    int tl0 = tok + 32, tl1 = tok + 40;
                    __half* t0 = Kf + ((size_t)(bh * KNT + (tl0 >> 3))) * 512 + kt * 128;
                    __half* t1 = Kf + ((size_t)(bh * KNT + (tl1 >> 3))) * 512 + kt * 128;
                    ((__half2*)t0)[b_off_h(d & 15, tl0 & 7) >> 1] = __floats2half2_rn(va0, vb0);
                    ((__half2*)t1)[b_off_h(d & 15, tl1 & 7) >> 1] = __floats2half2_rn(va1, vb1);
                } else {
                    int nt = d >> 3;
                    int tl0 = tok + 32, tl1 = tok + 40;
                    __half* base = Vf + ((size_t)(bh * 8 + nt)) * (VKT * 128);
                    __half* t0 = base + (tl0 >> 4) * 128;
                    __half* t1 = base + (tl1 >> 4) * 128;
                    t0[b_off_h(tl0 & 15, d & 7)]       = __float2half_rn(va0);
                    t0[b_off_h(tl0 & 15, (d + 1) & 7)] = __float2half_rn(vb0);
                    t1[b_off_h(tl1 & 15, d & 7)]       = __float2half_rn(va1);
                    t1[b_off_h(tl1 & 15, (d + 1) & 7)] = __float2half_rn(vb1);
                }
            }
        }
    }
}

// ============================================================
// Banded MMA attention (unchanged)
// ============================================================
#define AQT 64
#define SQ_B 0
#define SK_B 8192
#define SV_B 24576
#define SP_B 40960
#define SH_B 61440
#define SI_B 71680
#define ATT_SMEM (71680 + 256)

__global__ __launch_bounds__(256, 2)
void attn_kernel(const __half* __restrict__ QfG,
                 const __half* __restrict__ KfG,
                 const __half* __restrict__ VfG,
                 __half* __restrict__ Ox)
{
    extern __shared__ char smc[];
    uint32_t sb = smem_u32(smc);
    float*  Pf  = (float*) (smc + SP_B);
    __half* Ph  = (__half*)(smc + SH_B);
    float*  inv = (float*) (smc + SI_B);

    int tid = threadIdx.x;
    int q0  = blockIdx.x * AQT;
    int h   = blockIdx.y;
    int b   = blockIdx.z;
    int bh  = b * NUM_HEADS + h;

    {
        const char* qsrc = (const char*)(QfG + ((size_t)bh * (SEQ / 16) + (q0 >> 4)) * 1024);
        #pragma unroll
        for (int p = 0; p < 2; p++) {
            int ch = tid + p * 256;
            cp_async16(sb + SQ_B + ch * 16, qsrc + ch * 16);
        }
        const char* ksrc = (const char*)(KfG + ((size_t)bh * KNT + (q0 >> 3)) * 512);
        #pragma unroll
        for (int p = 0; p < 4; p++) {
            int ch = tid + p * 256;
            cp_async16(sb + SK_B + ch * 16, ksrc + ch * 16);
        }
        #pragma unroll
        for (int p = 0; p < 4; p++) {
            int ch = tid + p * 256;
            int nt = ch >> 7, in = ch & 127;
            const char* vsrc = (const char*)(VfG + ((size_t)(bh * 8 + nt)) * (VKT * 128) + (size_t)(q0 >> 4) * 128);
            cp_async16(sb + SV_B + ch * 16, vsrc + in * 16);
        }
        cp_commit();
        cp_wait<0>();
    }
    __syncthreads();

    int w  = tid >> 5;
    int L  = tid & 31;
    int mt = w >> 1;
    int half = w & 1;

    // ---- GEMM1: banded S = Q K^T ----
    {
        uint32_t qbase = sb + SQ_B;
        uint32_t kbase = sb + SK_B;
        uint32_t af[4][4];
        #pragma unroll
        for (int kt = 0; kt < 4; kt++)
            lds128(af[kt], qbase + (uint32_t)(mt * 4 + kt) * 512 + L * 16);
        #pragma unroll
        for (int nn = 0; nn < 5; nn++) {
            int ntl = half * 5 + nn;
            int ntg = 2 * mt + ntl;
            float acc[4] = {0.f, 0.f, 0.f, 0.f};
            #pragma unroll
            for (int kt = 0; kt < 4; kt++) {
                uint32_t bfr[2];
                lds64(bfr, kbase + (uint32_t)(ntg * 4 + kt) * 256 + L * 8);
                mma_f16(acc, af[kt], bfr);
            }
            int r = L >> 2, c = (L & 3) * 2;
            float* Pt = Pf + (mt * 10 + ntl) * 128;
            Pt[c_off(r, c)]         = acc[0];
            Pt[c_off(r, c + 1)]     = acc[1];
            Pt[c_off(r + 8, c)]     = acc[2];
            Pt[c_off(r + 8, c + 1)] = acc[3];
        }
    }
    __syncthreads();

    // ---- softmax ----
    {
        int row  = tid >> 2;
        int part = tid & 3;
        int rmt = row >> 4, r = row & 15;
        float* Pb = Pf + rmt * 10 * 128;
        __half* Pw = Ph + rmt * 5 * 256;
        int jb = rmt * 16;

        float mx = -1e30f;
        #pragma unroll
        for (int u = 0; u < 20; u++) {
            int jl = part * 20 + u;
            int J  = jb + jl;
            int gk = q0 - WINDOW + J;
            bool valid = (J >= row) && (J <= row + 64) && (gk >= 0) && (gk < SEQ);
            float s = Pb[(jl >> 3) * 128 + c_off(r, jl & 7)];
            if (valid) mx = fmaxf(mx, s);
        }
        mx = fmaxf(mx, __shfl_xor_sync(0xffffffffu, mx, 1));
        mx = fmaxf(mx, __shfl_xor_sync(0xffffffffu, mx, 2));

        float sum = 0.f;
        #pragma unroll
        for (int u = 0; u < 20; u++) {
            int jl = part * 20 + u;
            int J  = jb + jl;
            int gk = q0 - WINDOW + J;
            bool valid = (J >= row) && (J <= row + 64) && (gk >= 0) && (gk < SEQ);
            float s = Pb[(jl >> 3) * 128 + c_off(r, jl & 7)];
            float e = valid ? __expf(s - mx) : 0.f;
            sum += e;
            Pw[(jl >> 4) * 256 + a_off_h(r, jl & 15)] = __float2half_rn(e);
        }
        sum += __shfl_xor_sync(0xffffffffu, sum, 1);
        sum += __shfl_xor_sync(0xffffffffu, sum, 2);
        if (part == 0) inv[row] = 1.0f / sum;
    }
    __syncthreads();

    // ---- GEMM2: O = P V ----
    {
        uint32_t pbase = sb + SH_B;
        uint32_t vbase = sb + SV_B;
        int ntd0 = half * 4;
        float acc2[4][4];
        #pragma unroll
        for (int j = 0; j < 4; j++)
            #pragma unroll
            for (int q = 0; q < 4; q++) acc2[j][q] = 0.f;

        #pragma unroll
        for (int ktl = 0; ktl < 5; ktl++) {
            int kt_tok = mt + ktl;
            uint32_t af[4];
            lds128(af, pbase + (uint32_t)(mt * 5 + ktl) * 512 + L * 16);
            #pragma unroll
            for (int jn = 0; jn < 4; jn++) {
                uint32_t bfr[2];
                lds64(bfr, vbase + (uint32_t)((ntd0 + jn) * 8 + kt_tok) * 256 + L * 8);
                mma_f16(acc2[jn], af, bfr);
            }
        }

        int r0 = mt * 16 + (L >> 2);
        float i0 = inv[r0], i1 = inv[r0 + 8];
        int grow0 = b * SEQ + q0 + r0;
        int grow1 = grow0 + 8;
        int gmt0 = grow0 >> 4, grr0 = grow0 & 15;
        int gmt1 = grow1 >> 4, grr1 = grow1 & 15;
        #pragma unroll
        for (int jn = 0; jn < 4; jn++) {
            int col = h * HEAD_DIM + (ntd0 + jn) * 8 + (L & 3) * 2;
            int kt = col >> 4, cc = col & 15;
            __half2* t0 = (__half2*)(Ox + ((size_t)gmt0 * KT16 + kt) * 256);
            __half2* t1 = (__half2*)(Ox + ((size_t)gmt1 * KT16 + kt) * 256);
            t0[a_off_h(grr0, cc) >> 1] = __floats2half2_rn(acc2[jn][0] * i0, acc2[jn][1] * i0);
            t1[a_off_h(grr1, cc) >> 1] = __floats2half2_rn(acc2[jn][2] * i1, acc2[jn][3] * i1);
        }
    }
}

// ============================================================
// launch
// ============================================================
extern "C" void kernel_launch(void* const* d_in, const int* in_sizes, int n_in,
                              void* d_out, int out_size)
{
    (void)in_sizes; (void)n_in; (void)out_size;
    const float* x     = (const float*)d_in[0];
    const float* w_q   = (const float*)d_in[1];
    const float* b_q   = (const float*)d_in[2];
    const float* w_k   = (const float*)d_in[3];
    const float* b_k   = (const float*)d_in[4];
    const float* w_v   = (const float*)d_in[5];
    const float* b_v   = (const float*)d_in[6];
    const float* w_o   = (const float*)d_in[7];
    const float* b_o   = (const float*)d_in[8];
    const float* gamma = (const float*)d_in[9];
    const float* beta  = (const float*)d_in[10];
    float* out = (float*)d_out;

    void *pHx, *pWqkv, *pWo, *pBq, *pQf, *pKf, *pVf, *pAx;
    cudaGetSymbolAddress(&pHx,   g_Hx);
    cudaGetSymbolAddress(&pWqkv, g_Wqkv);
    cudaGetSymbolAddress(&pWo,   g_Wo);
    cudaGetSymbolAddress(&pBq,   g_bqkv);
    cudaGetSymbolAddress(&pQf,   g_QfG);
    cudaGetSymbolAddress(&pKf,   g_KfG);
    cudaGetSymbolAddress(&pVf,   g_VfG);
    cudaGetSymbolAddress(&pAx,   g_ATTx);
    __half* Hx   = (__half*)pHx;
    __half* Wqkv = (__half*)pWqkv;
    __half* Wo   = (__half*)pWo;
    float*  bqkv = (float*)pBq;
    __half* QfG  = (__half*)pQf;
    __half* KfG  = (__half*)pKf;
    __half* VfG  = (__half*)pVf;
    __half* ATTx = (__half*)pAx;

    cudaFuncSetAttribute(mm_kernel<0>, cudaFuncAttributeMaxDynamicSharedMemorySize, MM_SMEM);
    cudaFuncSetAttribute(mm_kernel<1>, cudaFuncAttributeMaxDynamicSharedMemorySize, MM_SMEM);
    cudaFuncSetAttribute(attn_kernel, cudaFuncAttributeMaxDynamicSharedMemorySize, ATT_SMEM);

    // prep
    wconv_kernel<<<dim3(1024 * 1024 / 256, 4), 256>>>(w_q, w_k, w_v, w_o, Wqkv, Wo);
    bconcat_kernel<<<(QKV_LD + 255) / 256, 256>>>(b_q, b_k, b_v, bqkv);
    ln_kernel<<<MROWS, 256>>>(x, gamma, beta, Hx);

    // fused QKV GEMM -> fragment arrays
    dim3 gq(QKV_LD / BN, MROWS / BM);     // (24, 32)
    mm_kernel<0><<<gq, MM_THREADS, MM_SMEM>>>(Hx, Wqkv, bqkv, nullptr, nullptr, 0, QfG, KfG, VfG);

    // banded MMA attention
    dim3 ga(SEQ / AQT, NUM_HEADS, BATCH); // (32, 16, 2)
    attn_kernel<<<ga, 256, ATT_SMEM>>>(QfG, KfG, VfG, ATTx);

    // output projection + bias + residual
    dim3 go(MODEL_DIM / BN, MROWS / BM);  // (8, 32)
    mm_kernel<1><<<go, MM_THREADS, MM_SMEM>>>(ATTx, Wo, b_o, x, out, MODEL_DIM, nullptr, nullptr, nullptr);
}

// round 17
// speedup vs baseline: 1.0278x; 1.0278x over previous
#include <cuda_runtime.h>
#include <cuda_fp16.h>
#include <cstdint>
#include <math.h>

// ---------------- problem constants ----------------
#define MODEL_DIM 1024
#define NUM_HEADS 16
#define HEAD_DIM  64
#define WINDOW    32
#define EPS       1e-5f
#define BATCH     2
#define SEQ       2048
#define MROWS     (BATCH * SEQ)      // 4096
#define QKV_LD    (3 * MODEL_DIM)    // 3072
#define KDIM      MODEL_DIM          // 1024
#define KT16      (KDIM / 16)        // 64

#define KNT 264                       // (2048+64)/8 n-tiles (padded)
#define VKT 132                       // (2048+64)/16 k-tiles (padded)

// ---------------- scratch (fragment-ordered fp16) ----------------
__device__ __half g_Hx  [(MROWS / 16) * KT16 * 256];
__device__ __half g_Wqkv[(QKV_LD / 8) * KT16 * 128];
__device__ __half g_Wo  [(MODEL_DIM / 8) * KT16 * 128];
__device__ float  g_bqkv[QKV_LD];
__device__ __half g_QfG [BATCH * NUM_HEADS * (SEQ / 16) * 1024];
__device__ __half g_KfG [BATCH * NUM_HEADS * KNT * 512];
__device__ __half g_VfG [BATCH * NUM_HEADS * 8 * VKT * 128];
__device__ __half g_ATTx[(MROWS / 16) * KT16 * 256];

// ---------------- helpers ----------------
__device__ __forceinline__ uint32_t smem_u32(const void* p) {
    uint32_t a;
    asm("{ .reg .u64 t; cvta.to.shared.u64 t, %1; cvt.u32.u64 %0, t; }" : "=r"(a) : "l"(p));
    return a;
}
__device__ __forceinline__ void cp_async16(uint32_t dst, const void* src) {
    asm volatile("cp.async.cg.shared.global [%0], [%1], 16;" :: "r"(dst), "l"(src) : "memory");
}
__device__ __forceinline__ void cp_commit() {
    asm volatile("cp.async.commit_group;" ::: "memory");
}
template<int N>
__device__ __forceinline__ void cp_wait() {
    asm volatile("cp.async.wait_group %0;" :: "n"(N) : "memory");
}
__device__ __forceinline__ void lds128(uint32_t* r, uint32_t a) {
    asm volatile("ld.shared.v4.b32 {%0,%1,%2,%3}, [%4];"
                 : "=r"(r[0]), "=r"(r[1]), "=r"(r[2]), "=r"(r[3]) : "r"(a));
}
__device__ __forceinline__ void lds64(uint32_t* r, uint32_t a) {
    asm volatile("ld.shared.v2.b32 {%0,%1}, [%2];"
                 : "=r"(r[0]), "=r"(r[1]) : "r"(a));
}
__device__ __forceinline__ void mma_f16(float* c, const uint32_t* a, const uint32_t* b) {
    asm volatile("mma.sync.aligned.m16n8k16.row.col.f32.f16.f16.f32 "
                 "{%0,%1,%2,%3},{%4,%5,%6,%7},{%8,%9},{%0,%1,%2,%3};"
                 : "+f"(c[0]), "+f"(c[1]), "+f"(c[2]), "+f"(c[3])
                 : "r"(a[0]), "r"(a[1]), "r"(a[2]), "r"(a[3]), "r"(b[0]), "r"(b[1]));
}
// two exponentials per MUFU op
__device__ __forceinline__ uint32_t ex2_f16x2(uint32_t x) {
    uint32_t y;
    asm("ex2.approx.f16x2 %0, %1;" : "=r"(y) : "r"(x));
    return y;
}

// fragment maps (half index within tile)
__device__ __forceinline__ int a_off_h(int rr, int cc) {
    return ((rr & 7) * 4 + ((cc & 7) >> 1)) * 8 + ((rr >> 3) + 2 * (cc >> 3)) * 2 + (cc & 1);
}
__device__ __forceinline__ int b_off_h(int k, int n) {
    return (n * 4 + ((k & 7) >> 1)) * 4 + (k >> 3) * 2 + (k & 1);
}
__device__ __forceinline__ int c_off(int rr, int cc) {
    return ((rr & 7) * 4 + (cc >> 1)) * 4 + (rr >> 3) * 2 + (cc & 1);
}

// ============================================================
// LayerNorm -> A-fragment-ordered fp16
// ============================================================
__global__ __launch_bounds__(256)
void ln_kernel(const float* __restrict__ x,
               const float* __restrict__ gamma,
               const float* __restrict__ beta,
               __half* __restrict__ Hx)
{
    int row = blockIdx.x;
    int tid = threadIdx.x;
    float4 a = ((const float4*)(x + (size_t)row * MODEL_DIM))[tid];

    __shared__ float red[8];
    __shared__ float stat;

    float s = a.x + a.y + a.z + a.w;
    #pragma unroll
    for (int o = 16; o; o >>= 1) s += __shfl_xor_sync(0xffffffffu, s, o);
    if ((tid & 31) == 0) red[tid >> 5] = s;
    __syncthreads();
    if (tid == 0) {
        float t = 0.f;
        #pragma unroll
        for (int i = 0; i < 8; i++) t += red[i];
        stat = t * (1.0f / MODEL_DIM);
    }
    __syncthreads();
    float mu = stat;

    float dx = a.x - mu, dy = a.y - mu, dz = a.z - mu, dw = a.w - mu;
    float s2 = dx*dx + dy*dy + dz*dz + dw*dw;
    #pragma unroll
    for (int o = 16; o; o >>= 1) s2 += __shfl_xor_sync(0xffffffffu, s2, o);
    __syncthreads();
    if ((tid & 31) == 0) red[tid >> 5] = s2;
    __syncthreads();
    if (tid == 0) {
        float t = 0.f;
        #pragma unroll
        for (int i = 0; i < 8; i++) t += red[i];
        stat = rsqrtf(t * (1.0f / MODEL_DIM) + EPS);
    }
    __syncthreads();
    float rstd = stat;

    float4 g = ((const float4*)gamma)[tid];
    float4 b = ((const float4*)beta)[tid];
    float v0 = dx * rstd * g.x + b.x;
    float v1 = dy * rstd * g.y + b.y;
    float v2 = dz * rstd * g.z + b.z;
    float v3 = dw * rstd * g.w + b.w;

    int mt = row >> 4, r = row & 15;
    int kt = tid >> 2;
    int cc0 = (tid * 4) & 15;
    __half* tile = Hx + ((size_t)mt * KT16 + kt) * 256;
    ((__half2*)tile)[a_off_h(r, cc0) >> 1]     = __floats2half2_rn(v0, v1);
    ((__half2*)tile)[a_off_h(r, cc0 + 2) >> 1] = __floats2half2_rn(v2, v3);
}

// ============================================================
// Weight -> B-fragment-ordered fp16 (+ fused bias concat)
// ============================================================
__global__ __launch_bounds__(256)
void wconv_kernel(const float* __restrict__ wq, const float* __restrict__ wk,
                  const float* __restrict__ wv, const float* __restrict__ wo,
                  const float* __restrict__ bq, const float* __restrict__ bk,
                  const float* __restrict__ bv,
                  __half* __restrict__ Wqkv, __half* __restrict__ Wo,
                  float* __restrict__ bqkv)
{
    int bz = blockIdx.y;
    const float* w = (bz == 0) ? wq : (bz == 1) ? wk : (bz == 2) ? wv : wo;
    __half* WT = (bz < 3) ? (Wqkv + (size_t)bz * (1024 / 8) * KT16 * 128) : Wo;

    int idx = blockIdx.x * 256 + threadIdx.x;
    int k = idx >> 10;
    int n = idx & 1023;
    float v = w[idx];
    int nt = n >> 3, kt = k >> 4;
    WT[((size_t)nt * KT16 + kt) * 128 + b_off_h(k & 15, n & 7)] = __float2half_rn(v);

    // fused bias concat (first 12 blocks of bz==3 cover 3072 elements)
    if (bz == 3 && blockIdx.x < 12) {
        int i = blockIdx.x * 256 + threadIdx.x;
        const float* s = (i < 1024) ? bq : (i < 2048 ? bk : bv);
        bqkv[i] = s[i & 1023];
    }
}

// ============================================================
// fp16 mma.sync GEMM. CTA 128x128x64, 4 warps (64x64).
// A: 3-stage cp.async smem.  B: direct coalesced LDG.64 of
// fragment-ordered global data (no smem round-trip).
// ============================================================
#define BM 128
#define BN 128
#define BK 64
#define A_TILE 16384                  // 8mt x 4kt x 512B
#define NSTAGE 3
#define NIT (KDIM / BK)               // 16
#define MM_SMEM (NSTAGE * A_TILE)     // 49152
#define MM_THREADS 128

__device__ __forceinline__ void stage_A(const __half* __restrict__ src,
                                        int mt0, int kt0, uint32_t dst)
{
    #pragma unroll
    for (int p = 0; p < 8; p++) {
        int ch = threadIdx.x + p * MM_THREADS;   // 1024 chunks of 16B
        int tl = ch >> 5;                        // 32 tiles (mti*4+kti)
        int in = ch & 31;
        int mti = tl >> 2, kti = tl & 3;
        const char* g = (const char*)(src + ((size_t)(mt0 + mti) * KT16 + kt0 + kti) * 256) + in * 16;
        cp_async16(dst + (uint32_t)tl * 512 + in * 16, g);
    }
}

template<int MODE>
__global__ __launch_bounds__(MM_THREADS, 2)
void mm_kernel(const __half* __restrict__ A,
               const __half* __restrict__ B,
               const float* __restrict__ bias,
               const float* __restrict__ resid,
               float* __restrict__ C, int ldc,
               __half* __restrict__ Qf, __half* __restrict__ Kf, __half* __restrict__ Vf)
{
    extern __shared__ char smem[];
    uint32_t sb = smem_u32(smem);

    int tid  = threadIdx.x;
    int wid  = tid >> 5;
    int lane = tid & 31;
    int mtb = (wid >> 1) * 4;
    int ntb = (wid & 1) * 8;
    int mt0 = blockIdx.y * 8;
    int nt0 = blockIdx.x * 16;

    float acc[4][8][4];
    #pragma unroll
    for (int i = 0; i < 4; i++)
        #pragma unroll
        for (int j = 0; j < 8; j++)
            #pragma unroll
            for (int q = 0; q < 4; q++) acc[i][j][q] = 0.f;

    stage_A(A, mt0, 0, sb);
    cp_commit();
    stage_A(A, mt0, 4, sb + A_TILE);
    cp_commit();

    uint32_t aoff = (uint32_t)lane * 16;
    // B fragment tile = 128 halves = 32 uint2; thread L's fragment = tile_base + L.
    const uint2* Bbase = (const uint2*)(B + ((size_t)(nt0 + ntb) * KT16) * 128) + lane;

    #pragma unroll 1
    for (int it = 0; it < NIT; it++) {
        cp_wait<1>();
        __syncthreads();

        if (it + 2 < NIT) {
            uint32_t nb = sb + (uint32_t)((it + 2) % NSTAGE) * A_TILE;
            stage_A(A, mt0, (it + 2) * 4, nb);
        }
        cp_commit();

        uint32_t aB = sb + (uint32_t)(it % NSTAGE) * A_TILE;

        #pragma unroll
        for (int kti = 0; kti < 4; kti++) {
            int ktg = it * 4 + kti;
            uint32_t af[4][4];
            uint2 bv[8];
            #pragma unroll
            for (int j = 0; j < 8; j++)
                bv[j] = __ldg(Bbase + ((size_t)j * KT16 + ktg) * 32);   // tile = 32 uint2
            #pragma unroll
            for (int i = 0; i < 4; i++)
                lds128(af[i], aB + (uint32_t)((mtb + i) * 4 + kti) * 512 + aoff);
            #pragma unroll
            for (int i = 0; i < 4; i++)
                #pragma unroll
                for (int j = 0; j < 8; j++) {
                    uint32_t br[2] = {bv[j].x, bv[j].y};
                    mma_f16(acc[i][j], af[i], br);
                }
        }
    }

    int mBase = mt0 * 16 + mtb * 16 + (lane >> 2);
    int nBase = nt0 * 8 + ntb * 8 + (lane & 3) * 2;

    if (MODE == 1) {
        #pragma unroll
        for (int i = 0; i < 4; i++) {
            int m0 = mBase + i * 16;
            #pragma unroll
            for (int j = 0; j < 8; j++) {
                int n = nBase + j * 8;
                float bx0 = bias[n], bx1 = bias[n + 1];
                float2 v0, v1;
                v0.x = acc[i][j][0] + bx0;
                v0.y = acc[i][j][1] + bx1;
                v1.x = acc[i][j][2] + bx0;
                v1.y = acc[i][j][3] + bx1;
                float2 r0 = *(const float2*)(resid + (size_t)m0 * MODEL_DIM + n);
                float2 r1 = *(const float2*)(resid + (size_t)(m0 + 8) * MODEL_DIM + n);
                v0.x += r0.x; v0.y += r0.y;
                v1.x += r1.x; v1.y += r1.y;
                *(float2*)(C + (size_t)m0 * ldc + n)       = v0;
                *(float2*)(C + (size_t)(m0 + 8) * ldc + n) = v1;
            }
        }
    } else {
        int mtype = (nt0 * 8) >> 10;   // 0=Q 1=K 2=V (uniform per CTA)
        #pragma unroll
        for (int i = 0; i < 4; i++) {
            int m0 = mBase + i * 16;
            int bb  = m0 >> 11;
            int tok = m0 & 2047;
            #pragma unroll
            for (int j = 0; j < 8; j++) {
                int n = nBase + j * 8;
                float bx0 = bias[n], bx1 = bias[n + 1];
                float va0 = acc[i][j][0] + bx0, vb0 = acc[i][j][1] + bx1;
                float va1 = acc[i][j][2] + bx0, vb1 = acc[i][j][3] + bx1;
                int nn = n & 1023;
                int h = nn >> 6, d = nn & 63;
                int bh = bb * NUM_HEADS + h;
                if (mtype == 0) {
                    int kt = d >> 4, cc = d & 15;
                    __half2 h0 = __floats2half2_rn(va0 * 0.125f, vb0 * 0.125f);
                    __half2 h1 = __floats2half2_rn(va1 * 0.125f, vb1 * 0.125f);
                    __half* t0 = Qf + ((size_t)(bh * (SEQ / 16) + (tok >> 4))) * 1024 + kt * 256;
                    __half* t1 = Qf + ((size_t)(bh * (SEQ / 16) + ((tok + 8) >> 4))) * 1024 + kt * 256;
                    ((__half2*)t0)[a_off_h(tok & 15, cc) >> 1]       = h0;
                    ((__half2*)t1)[a_off_h((tok + 8) & 15, cc) >> 1] = h1;
                } else if (mtype == 1) {
                    int kt = d >> 4;
                    int tl0 = tok + 32, tl1 = tok + 40;
                    __half* t0 = Kf + ((size_t)(bh * KNT + (tl0 >> 3))) * 512 + kt * 128;
                    __half* t1 = Kf + ((size_t)(bh * KNT + (tl1 >> 3))) * 512 + kt * 128;
                    ((__half2*)t0)[b_off_h(d & 15, tl0 & 7) >> 1] = __floats2half2_rn(va0, vb0);
                    ((__half2*)t1)[b_off_h(d & 15, tl1 & 7) >> 1] = __floats2half2_rn(va1, vb1);
                } else {
                    int nt = d >> 3;
                    int tl0 = tok + 32, tl1 = tok + 40;
                    __half* base = Vf + ((size_t)(bh * 8 + nt)) * (VKT * 128);
                    __half* t0 = base + (tl0 >> 4) * 128;
                    __half* t1 = base + (tl1 >> 4) * 128;
                    t0[b_off_h(tl0 & 15, d & 7)]       = __float2half_rn(va0);
                    t0[b_off_h(tl0 & 15, (d + 1) & 7)] = __float2half_rn(vb0);
                    t1[b_off_h(tl1 & 15, d & 7)]       = __float2half_rn(va1);
                    t1[b_off_h(tl1 & 15, (d + 1) & 7)] = __float2half_rn(vb1);
                }
            }
        }
    }
}

// ============================================================
// Banded MMA attention; softmax exp via ex2.approx.f16x2
// (2 exponentials per MUFU op).
// ============================================================
#define AQT 64
#define SQ_B 0
#define SK_B 8192
#define SV_B 24576
#define SP_B 40960
#define SH_B 61440
#define SI_B 71680
#define ATT_SMEM (71680 + 256)

__global__ __launch_bounds__(256, 2)
void attn_kernel(const __half* __restrict__ QfG,
                 const __half* __restrict__ KfG,
                 const __half* __restrict__ VfG,
                 __half* __restrict__ Ox)
{
    extern __shared__ char smc[];
    uint32_t sb = smem_u32(smc);
    float*  Pf  = (float*) (smc + SP_B);
    __half* Ph  = (__half*)(smc + SH_B);
    float*  inv = (float*) (smc + SI_B);

    int tid = threadIdx.x;
    int q0  = blockIdx.x * AQT;
    int h   = blockIdx.y;
    int b   = blockIdx.z;
    int bh  = b * NUM_HEADS + h;

    {
        const char* qsrc = (const char*)(QfG + ((size_t)bh * (SEQ / 16) + (q0 >> 4)) * 1024);
        #pragma unroll
        for (int p = 0; p < 2; p++) {
            int ch = tid + p * 256;
            cp_async16(sb + SQ_B + ch * 16, qsrc + ch * 16);
        }
        const char* ksrc = (const char*)(KfG + ((size_t)bh * KNT + (q0 >> 3)) * 512);
        #pragma unroll
        for (int p = 0; p < 4; p++) {
            int ch = tid + p * 256;
            cp_async16(sb + SK_B + ch * 16, ksrc + ch * 16);
        }
        #pragma unroll
        for (int p = 0; p < 4; p++) {
            int ch = tid + p * 256;
            int nt = ch >> 7, in = ch & 127;
            const char* vsrc = (const char*)(VfG + ((size_t)(bh * 8 + nt)) * (VKT * 128) + (size_t)(q0 >> 4) * 128);
            cp_async16(sb + SV_B + ch * 16, vsrc + in * 16);
        }
        cp_commit();
        cp_wait<0>();
    }
    __syncthreads();

    int w  = tid >> 5;
    int L  = tid & 31;
    int mt = w >> 1;
    int half = w & 1;

    // ---- GEMM1: banded S = Q K^T ----
    {
        uint32_t qbase = sb + SQ_B;
        uint32_t kbase = sb + SK_B;
        uint32_t af[4][4];
        #pragma unroll
        for (int kt = 0; kt < 4; kt++)
            lds128(af[kt], qbase + (uint32_t)(mt * 4 + kt) * 512 + L * 16);
        #pragma unroll
        for (int nn = 0; nn < 5; nn++) {
            int ntl = half * 5 + nn;
            int ntg = 2 * mt + ntl;
            float acc[4] = {0.f, 0.f, 0.f, 0.f};
            #pragma unroll
            for (int kt = 0; kt < 4; kt++) {
                uint32_t bfr[2];
                lds64(bfr, kbase + (uint32_t)(ntg * 4 + kt) * 256 + L * 8);
                mma_f16(acc, af[kt], bfr);
            }
            int r = L >> 2, c = (L & 3) * 2;
            float* Pt = Pf + (mt * 10 + ntl) * 128;
            Pt[c_off(r, c)]         = acc[0];
            Pt[c_off(r, c + 1)]     = acc[1];
            Pt[c_off(r + 8, c)]     = acc[2];
            Pt[c_off(r + 8, c + 1)] = acc[3];
        }
    }
    __syncthreads();

    // ---- softmax (exp in f16x2, 2 per MUFU op) ----
    {
        int row  = tid >> 2;
        int part = tid & 3;
        int rmt = row >> 4, r = row & 15;
        float* Pb = Pf + rmt * 10 * 128;
        __half* Pw = Ph + rmt * 5 * 256;
        int jb = rmt * 16;

        float mx = -1e30f;
        #pragma unroll
        for (int u = 0; u < 20; u++) {
            int jl = part * 20 + u;
            int J  = jb + jl;
            int gk = q0 - WINDOW + J;
            bool valid = (J >= row) && (J <= row + 64) && (gk >= 0) && (gk < SEQ);
            float s = Pb[(jl >> 3) * 128 + c_off(r, jl & 7)];
            if (valid) mx = fmaxf(mx, s);
        }
        mx = fmaxf(mx, __shfl_xor_sync(0xffffffffu, mx, 1));
        mx = fmaxf(mx, __shfl_xor_sync(0xffffffffu, mx, 2));

        const float L2E = 1.44269504f;
        float sum = 0.f;
        #pragma unroll
        for (int u = 0; u < 20; u += 2) {
            int jl = part * 20 + u;             // even
            int J  = jb + jl;
            int gk = q0 - WINDOW + J;
            bool v0ok = (J >= row) && (J <= row + 64) && (gk >= 0) && (gk < SEQ);
            bool v1ok = (J + 1 >= row) && (J + 1 <= row + 64) && (gk + 1 >= 0) && (gk + 1 < SEQ);
            float s0 = Pb[(jl >> 3) * 128 + c_off(r, jl & 7)];
            float s1 = Pb[((jl + 1) >> 3) * 128 + c_off(r, (jl + 1) & 7)];
            float t0 = v0ok ? (s0 - mx) * L2E : -100.f;
            float t1 = v1ok ? (s1 - mx) * L2E : -100.f;
            __half2 hx = __floats2half2_rn(t0, t1);
            uint32_t eb = ex2_f16x2(*(uint32_t*)&hx);
            __half2 eh = *(__half2*)&eb;
            float2 ef = __half22float2(eh);
            sum += ef.x + ef.y;
            // jl even -> a_off_h(r, jl&15) is even and jl,jl+1 are adjacent halves
            ((__half2*)Pw)[((jl >> 4) * 256 + a_off_h(r, jl & 15)) >> 1] = eh;
        }
        sum += __shfl_xor_sync(0xffffffffu, sum, 1);
        sum += __shfl_xor_sync(0xffffffffu, sum, 2);
        if (part == 0) inv[row] = 1.0f / sum;
    }
    __syncthreads();

    // ---- GEMM2: O = P V ----
    {
        uint32_t pbase = sb + SH_B;
        uint32_t vbase = sb + SV_B;
        int ntd0 = half * 4;
        float acc2[4][4];
        #pragma unroll
        for (int j = 0; j < 4; j++)
            #pragma unroll
            for (int q = 0; q < 4; q++) acc2[j][q] = 0.f;

        #pragma unroll
        for (int ktl = 0; ktl < 5; ktl++) {
            int kt_tok = mt + ktl;
            uint32_t af[4];
            lds128(af, pbase + (uint32_t)(mt * 5 + ktl) * 512 + L * 16);
            #pragma unroll
            for (int jn = 0; jn < 4; jn++) {
                uint32_t bfr[2];
                lds64(bfr, vbase + (uint32_t)((ntd0 + jn) * 8 + kt_tok) * 256 + L * 8);
                mma_f16(acc2[jn], af, bfr);
            }
        }

        int r0 = mt * 16 + (L >> 2);
        float i0 = inv[r0], i1 = inv[r0 + 8];
        int grow0 = b * SEQ + q0 + r0;
        int grow1 = grow0 + 8;
        int gmt0 = grow0 >> 4, grr0 = grow0 & 15;
        int gmt1 = grow1 >> 4, grr1 = grow1 & 15;
        #pragma unroll
        for (int jn = 0; jn < 4; jn++) {
            int col = h * HEAD_DIM + (ntd0 + jn) * 8 + (L & 3) * 2;
            int kt = col >> 4, cc = col & 15;
            __half2* t0 = (__half2*)(Ox + ((size_t)gmt0 * KT16 + kt) * 256);
            __half2* t1 = (__half2*)(Ox + ((size_t)gmt1 * KT16 + kt) * 256);
            t0[a_off_h(grr0, cc) >> 1] = __floats2half2_rn(acc2[jn][0] * i0, acc2[jn][1] * i0);
            t1[a_off_h(grr1, cc) >> 1] = __floats2half2_rn(acc2[jn][2] * i1, acc2[jn][3] * i1);
        }
    }
}

// ============================================================
// launch
// ============================================================
extern "C" void kernel_launch(void* const* d_in, const int* in_sizes, int n_in,
                              void* d_out, int out_size)
{
    (void)in_sizes; (void)n_in; (void)out_size;
    const float* x     = (const float*)d_in[0];
    const float* w_q   = (const float*)d_in[1];
    const float* b_q   = (const float*)d_in[2];
    const float* w_k   = (const float*)d_in[3];
    const float* b_k   = (const float*)d_in[4];
    const float* w_v   = (const float*)d_in[5];
    const float* b_v   = (const float*)d_in[6];
    const float* w_o   = (const float*)d_in[7];
    const float* b_o   = (const float*)d_in[8];
    const float* gamma = (const float*)d_in[9];
    const float* beta  = (const float*)d_in[10];
    float* out = (float*)d_out;

    void *pHx, *pWqkv, *pWo, *pBq, *pQf, *pKf, *pVf, *pAx;
    cudaGetSymbolAddress(&pHx,   g_Hx);
    cudaGetSymbolAddress(&pWqkv, g_Wqkv);
    cudaGetSymbolAddress(&pWo,   g_Wo);
    cudaGetSymbolAddress(&pBq,   g_bqkv);
    cudaGetSymbolAddress(&pQf,   g_QfG);
    cudaGetSymbolAddress(&pKf,   g_KfG);
    cudaGetSymbolAddress(&pVf,   g_VfG);
    cudaGetSymbolAddress(&pAx,   g_ATTx);
    __half* Hx   = (__half*)pHx;
    __half* Wqkv = (__half*)pWqkv;
    __half* Wo   = (__half*)pWo;
    float*  bqkv = (float*)pBq;
    __half* QfG  = (__half*)pQf;
    __half* KfG  = (__half*)pKf;
    __half* VfG  = (__half*)pVf;
    __half* ATTx = (__half*)pAx;

    cudaFuncSetAttribute(mm_kernel<0>, cudaFuncAttributeMaxDynamicSharedMemorySize, MM_SMEM);
    cudaFuncSetAttribute(mm_kernel<1>, cudaFuncAttributeMaxDynamicSharedMemorySize, MM_SMEM);
    cudaFuncSetAttribute(attn_kernel, cudaFuncAttributeMaxDynamicSharedMemorySize, ATT_SMEM);

    // prep (bconcat fused into wconv)
    wconv_kernel<<<dim3(1024 * 1024 / 256, 4), 256>>>(w_q, w_k, w_v, w_o,
                                                      b_q, b_k, b_v,
                                                      Wqkv, Wo, bqkv);
    ln_kernel<<<MROWS, 256>>>(x, gamma, beta, Hx);

    // fused QKV GEMM -> fragment arrays
    dim3 gq(QKV_LD / BN, MROWS / BM);     // (24, 32)
    mm_kernel<0><<<gq, MM_THREADS, MM_SMEM>>>(Hx, Wqkv, bqkv, nullptr, nullptr, 0, QfG, KfG, VfG);

    // banded MMA attention
    dim3 ga(SEQ / AQT, NUM_HEADS, BATCH); // (32, 16, 2)
    attn_kernel<<<ga, 256, ATT_SMEM>>>(QfG, KfG, VfG, ATTx);

    // output projection + bias + residual
    dim3 go(MODEL_DIM / BN, MROWS / BM);  // (8, 32)
    mm_kernel<1><<<go, MM_THREADS, MM_SMEM>>>(ATTx, Wo, b_o, x, out, MODEL_DIM, nullptr, nullptr, nullptr);
}